// round 17
// baseline (speedup 1.0000x reference)
#include <cuda_runtime.h>
#include <cuda_fp16.h>
#include <math.h>

#define BB   8
#define CC   256
#define NN   4096
#define QKD  32
#define SCALE 0.17677669529663687f  /* 32^-0.5 */
#define L2E   1.44269504088896f

// ---------------- scratch ---------------------------------------------------
__device__ __align__(16) __half g_qh[BB*NN*QKD];   // fp16 q (scaled, +bq)
__device__ __align__(16) __half g_kh[BB*NN*QKD];   // fp16 k (+bk)
__device__ __align__(16) __half g_vth[BB*NN*CC];   // fp16 v [n][c] (+bv, unscaled)
__device__ float  g_invS[BB*NN];
__device__ float  g_Ml2[BB*NN];                    // M' * log2(e)
__device__ __align__(16) __half g_vh[(size_t)BB*CC*NN];  // [b][c][n] fp16, *invS
__device__ __align__(16) __half g_xh[(size_t)BB*NN*CC];  // attention out fp16 [m][c]
__device__ __align__(16) __half g_mlph[(size_t)BB*NN*CC];// mlp out fp16 [m][c]
__device__ __half g_W1h[CC*CC];              // [o][c] fp16
__device__ __half g_W2h[CC*CC];
__device__ float  g_kn2[BB*NN];
__device__ float  g_qmax[BB];
__device__ float  g_red[BB*64*2];
__device__ float  g_mv[BB*2];

// ---------------- helpers ----------------------------------------------------
__device__ __forceinline__ float tf32r(float x) {
    unsigned u;
    asm("cvt.rna.tf32.f32 %0, %1;" : "=r"(u) : "f"(x));
    return __uint_as_float(u);
}
__device__ __forceinline__ float fex2(float x) {
    float r;
    asm("ex2.approx.f32 %0, %1;" : "=f"(r) : "f"(x));
    return r;
}
__device__ __forceinline__ void mma8(float* c,
                                     unsigned a0, unsigned a1, unsigned a2, unsigned a3,
                                     unsigned b0, unsigned b1) {
    asm volatile("mma.sync.aligned.m16n8k8.row.col.f32.tf32.tf32.f32 "
                 "{%0,%1,%2,%3}, {%4,%5,%6,%7}, {%8,%9}, {%0,%1,%2,%3};\n"
                 : "+f"(c[0]), "+f"(c[1]), "+f"(c[2]), "+f"(c[3])
                 : "r"(a0), "r"(a1), "r"(a2), "r"(a3), "r"(b0), "r"(b1));
}
__device__ __forceinline__ void mma16(float* c,
                                      unsigned a0, unsigned a1, unsigned a2, unsigned a3,
                                      unsigned b0, unsigned b1) {
    asm volatile("mma.sync.aligned.m16n8k16.row.col.f32.f16.f16.f32 "
                 "{%0,%1,%2,%3}, {%4,%5,%6,%7}, {%8,%9}, {%0,%1,%2,%3};\n"
                 : "+f"(c[0]), "+f"(c[1]), "+f"(c[2]), "+f"(c[3])
                 : "r"(a0), "r"(a1), "r"(a2), "r"(a3), "r"(b0), "r"(b1));
}
#define FU  __float_as_uint
#define LH2(p) (*(const unsigned*)(p))
#define CPA(dst, src)  asm volatile("cp.async.cg.shared.global [%0], [%1], 16;\n" :: "r"(dst), "l"(src))
#define CPCOMMIT()     asm volatile("cp.async.commit_group;\n")
#define CPWAIT1()      asm volatile("cp.async.wait_group 1;\n" ::: "memory")
#define CPWAIT0()      asm volatile("cp.async.wait_group 0;\n" ::: "memory")
#define LDSM4(r0,r1,r2,r3,addr) \
    asm volatile("ldmatrix.sync.aligned.m8n8.x4.shared.b16 {%0,%1,%2,%3}, [%4];" \
                 : "=r"(r0), "=r"(r1), "=r"(r2), "=r"(r3) : "r"(addr))

__device__ __forceinline__ unsigned s2u(const void* p) {
    unsigned a;
    asm("{ .reg .u64 t; cvta.to.shared.u64 t, %1; cvt.u32.u64 %0, t; }" : "=r"(a) : "l"(p));
    return a;
}

// ---------------- weight prep + qmax zero ------------------------------------
__global__ void wprep(const float* __restrict__ W1, const float* __restrict__ W2) {
    int i = blockIdx.x*256 + threadIdx.x;
    if (i < 8) g_qmax[i] = 0.f;
    if (i < CC*CC) g_W1h[i] = __float2half(W1[i]);
    else           g_W2h[i - CC*CC] = __float2half(W2[i - CC*CC]);
}

// ---------------- q/k/v projection via tf32 mma ------------------------------
#define XS 72
__global__ void qkv_mma(const float* __restrict__ x,
                        const float* __restrict__ Wq, const float* __restrict__ bq,
                        const float* __restrict__ Wk, const float* __restrict__ bk,
                        const float* __restrict__ Wv, const float* __restrict__ bv) {
    __shared__ float xs[32*XS];
    __shared__ float ws[64*40];
    int b  = blockIdx.z;
    int o0 = blockIdx.y * 64;
    int n0 = blockIdx.x * 64;
    int tid = threadIdx.x, w = tid >> 5, lane = tid & 31, g = lane >> 2, tig = lane & 3;
    int sw = w & 3, np = w >> 2;
    const float* xb = x + (size_t)b * CC * NN;

    float acc[4][4];
#pragma unroll
    for (int i = 0; i < 4; i++)
#pragma unroll
        for (int j = 0; j < 4; j++) acc[i][j] = 0.f;

    for (int c0 = 0; c0 < CC; c0 += 32) {
        __syncthreads();
#pragma unroll
        for (int r = 0; r < 8; r++) {
            int e = r*256 + tid; int cc = e >> 6, nn = e & 63;
            xs[cc*XS + nn] = tf32r(xb[(c0 + cc)*NN + n0 + nn]);
        }
#pragma unroll
        for (int r = 0; r < 8; r++) {
            int e = r*256 + tid; int oo = e >> 5, cc = e & 31;
            int o = o0 + oo;
            const float* Wr = (o < 32) ? (Wq + o*CC)
                            : (o < 64) ? (Wk + (o-32)*CC)
                                       : (Wv + (o-64)*CC);
            ws[oo*40 + cc] = tf32r(Wr[c0 + cc]);
        }
        __syncthreads();
#pragma unroll
        for (int k4 = 0; k4 < 4; k4++) {
            int k0 = k4*8;
            unsigned a0 = FU(xs[(k0 + tig)*XS     + sw*16 + g]);
            unsigned a1 = FU(xs[(k0 + tig)*XS     + sw*16 + 8 + g]);
            unsigned a2 = FU(xs[(k0 + tig + 4)*XS + sw*16 + g]);
            unsigned a3 = FU(xs[(k0 + tig + 4)*XS + sw*16 + 8 + g]);
#pragma unroll
            for (int t8 = 0; t8 < 4; t8++) {
                int oc = np*32 + t8*8 + g;
                unsigned b0 = FU(ws[oc*40 + k0 + tig]);
                unsigned b1 = FU(ws[oc*40 + k0 + tig + 4]);
                mma8(acc[t8], a0, a1, a2, a3, b0, b1);
            }
        }
    }
#pragma unroll
    for (int t8 = 0; t8 < 4; t8++) {
#pragma unroll
        for (int rr = 0; rr < 2; rr++) {
            int n = n0 + sw*16 + g + rr*8;
            int o = o0 + np*32 + t8*8 + 2*tig;
            float v0 = acc[t8][rr*2 + 0];
            float v1 = acc[t8][rr*2 + 1];
            if (o < 32) {
                *(__half2*)(g_qh + (b*NN + n)*QKD + o) =
                    __floats2half2_rn((v0 + __ldg(bq + o)) * SCALE,
                                      (v1 + __ldg(bq + o + 1)) * SCALE);
            } else if (o < 64) {
                *(__half2*)(g_kh + (b*NN + n)*QKD + (o - 32)) =
                    __floats2half2_rn(v0 + __ldg(bk + o - 32),
                                      v1 + __ldg(bk + o - 31));
            } else {
                *(__half2*)(g_vth + (size_t)(b*NN + n)*CC + (o - 64)) =
                    __floats2half2_rn(v0 + __ldg(bv + o - 64),
                                      v1 + __ldg(bv + o - 63));
            }
        }
    }
}

// ---------------- norms: kn2 + block-max qn2 -> atomicMax qmax ---------------
__global__ void bound_norms() {
    __shared__ float s[256];
    int idx = blockIdx.x*256 + threadIdx.x;
    int b = idx >> 12;
    const __half* qp = g_qh + idx*QKD;
    const __half* kp = g_kh + idx*QKD;
    float qs = 0.f, ks = 0.f;
#pragma unroll
    for (int j = 0; j < QKD/2; j++) {
        float2 q2 = __half22float2(*(const __half2*)(qp + 2*j));
        float2 k2 = __half22float2(*(const __half2*)(kp + 2*j));
        qs = fmaf(q2.x, q2.x, qs); qs = fmaf(q2.y, q2.y, qs);
        ks = fmaf(k2.x, k2.x, ks); ks = fmaf(k2.y, k2.y, ks);
    }
    g_kn2[idx] = ks;
    s[threadIdx.x] = qs; __syncthreads();
    for (int st = 128; st > 0; st >>= 1) {
        if (threadIdx.x < st) s[threadIdx.x] = fmaxf(s[threadIdx.x], s[threadIdx.x + st]);
        __syncthreads();
    }
    if (threadIdx.x == 0)
        atomicMax((int*)&g_qmax[b], __float_as_int(s[0]));
}

// ---------------- stats6: logits(mma) -> exp2 -> S[n] only (no E store) ------
// smem: Mch 512B | ks 10240B | qs0 5120B | qs1 5120B = 20992B
__global__ void stats6() {
    extern __shared__ char smc[];
    float*  Mch = (float*)smc;
    __half* ks  = (__half*)(smc + 512);
    unsigned sb = s2u(smc);

    int b = blockIdx.y, n0 = blockIdx.x*128;
    int tid = threadIdx.x, w = tid >> 5, lane = tid & 31, g = lane >> 2, tig = lane & 3;

#pragma unroll
    for (int r = 0; r < 2; r++) {
        int e = r*256 + tid; int row = e >> 2, part = e & 3;
        *(uint4*)(ks + row*40 + part*8) =
            *(const uint4*)(g_kh + (b*NN + n0 + row)*QKD + part*8);
    }
    if (tid < 128) {
        float m = sqrtf(g_kn2[b*NN + n0 + tid] * g_qmax[b]) * L2E;
        Mch[tid] = m;
        g_Ml2[b*NN + n0 + tid] = m;
    }
    __syncthreads();

    unsigned bb[2][2][2];
#pragma unroll
    for (int t = 0; t < 2; t++) {
        int nb = w*16 + t*8;
#pragma unroll
        for (int k2 = 0; k2 < 2; k2++) {
            const __half* p = ks + (nb + g)*40 + k2*16 + 2*tig;
            bb[t][k2][0] = LH2(p);
            bb[t][k2][1] = LH2(p + 8);
        }
    }

    int qrow = tid >> 2, qc8 = (tid & 3)*8;
    const __half* qsrc = g_qh + ((size_t)(b*NN) + qrow)*QKD + qc8;
    unsigned qdst = sb + 10752 + (qrow*40 + qc8)*2;
    unsigned abase = sb + 10752 + ((lane & 15)*40 + ((lane & 16) >> 1))*2;
    CPA(qdst, qsrc); CPCOMMIT();

    float scol[4] = {0.f, 0.f, 0.f, 0.f};
    for (int it = 0; it < 64; it++) {
        if (it + 1 < 64) {
            CPA(qdst + ((it + 1) & 1)*5120, qsrc + (it + 1)*64*QKD);
            CPCOMMIT();
            CPWAIT1();
        } else {
            CPWAIT0();
        }
        __syncthreads();
        unsigned qb = abase + (it & 1)*5120;
#pragma unroll
        for (int sw = 0; sw < 4; sw++) {
            unsigned a[2][4];
            LDSM4(a[0][0], a[0][1], a[0][2], a[0][3], qb + sw*1280);
            LDSM4(a[1][0], a[1][1], a[1][2], a[1][3], qb + sw*1280 + 32);
#pragma unroll
            for (int t = 0; t < 2; t++) {
                float d[4] = {0.f, 0.f, 0.f, 0.f};
#pragma unroll
                for (int k2 = 0; k2 < 2; k2++)
                    mma16(d, a[k2][0], a[k2][1], a[k2][2], a[k2][3],
                          bb[t][k2][0], bb[t][k2][1]);
                int nb = w*16 + t*8;
                float M0 = Mch[nb + 2*tig], M1 = Mch[nb + 2*tig + 1];
                scol[t*2]     += fex2(fmaf(d[0], L2E, -M0)) + fex2(fmaf(d[2], L2E, -M0));
                scol[t*2 + 1] += fex2(fmaf(d[1], L2E, -M1)) + fex2(fmaf(d[3], L2E, -M1));
            }
        }
        __syncthreads();
    }
#pragma unroll
    for (int off = 16; off >= 4; off >>= 1)
#pragma unroll
        for (int i = 0; i < 4; i++)
            scol[i] += __shfl_down_sync(0xffffffffu, scol[i], off);
    if (lane < 4) {
#pragma unroll
        for (int t = 0; t < 2; t++)
#pragma unroll
            for (int p = 0; p < 2; p++) {
                int n = w*16 + t*8 + 2*lane + p;
                g_invS[b*NN + n0 + n] = 1.f / scol[t*2 + p];
            }
    }
}

// ---------------- vprep: g_vh[b][c][n] = half(v[n][c] * invS[n]) -------------
__global__ void vprep() {
    __shared__ float s[32][33];
    int b = blockIdx.z, c0 = blockIdx.y*32, n0 = blockIdx.x*32;
    int tx = threadIdx.x, ty = threadIdx.y;
#pragma unroll
    for (int r = 0; r < 4; r++) {
        int n = n0 + ty + 8*r;
        s[ty + 8*r][tx] = __half2float(g_vth[(size_t)(b*NN + n)*CC + c0 + tx])
                          * g_invS[b*NN + n];
    }
    __syncthreads();
#pragma unroll
    for (int r = 0; r < 4; r++) {
        int c = c0 + ty + 8*r;
        g_vh[((size_t)b*CC + c)*NN + n0 + tx] = __float2half(s[tx][ty + 8*r]);
    }
}

// ---------------- attnout7: fused logits+exp+PV, no E in HBM -----------------
// smem layout (halves):
//   qs  @ 0      : 128 x 40  = 5120
//   Es  @ 5120   : 128 x 72  = 9216
//   ks  @ 14336  : 2 stages x 64 x 40  = 2 x 2560
//   vs  @ 19456  : 2 stages x 256 x 72 = 2 x 18432
// total 56320 halves = 112640 B
#define A7_ES   5120
#define A7_KS   14336
#define A7_VS   19456
#define A7_KSB  5120      /* k stage size, bytes  */
#define A7_VSB  36864     /* v stage size, bytes  */
__global__ void __launch_bounds__(512, 1) attnout7() {
    extern __shared__ __half smh[];
    unsigned sb = s2u(smh);

    int b = blockIdx.y, m0 = blockIdx.x*128;
    int tid = threadIdx.x, lane = tid & 31, w = tid >> 5, g = lane >> 2, tig = lane & 3;
    int msub = w & 7, np = w >> 3;   // logits roles: m = msub*16, n-half = np*32
    int mw = w & 3,  cw = w >> 2;    // PV roles:     m = mw*32,  col = cw*64

    // ---- load q tile (128 x 32 halves = 512 uint4, 1/thread)
    {
        int row = tid >> 2, part = tid & 3;
        *(uint4*)(smh + row*40 + part*8) =
            *(const uint4*)(g_qh + ((size_t)(b*NN + m0 + row))*QKD + part*8);
    }

    // ---- cp.async mappings
    int krow = tid >> 2, kpart = tid & 3;          // tid<256: 64 rows x 4
    const __half* kS = g_kh + ((size_t)(b*NN) + krow)*QKD + kpart*8;
    unsigned kD = sb + (A7_KS + krow*40 + kpart*8)*2;
    int vr = tid >> 3, vp = (tid & 7)*8;           // 4 groups of 64 rows x 8
    const __half* vS[4]; unsigned vD[4];
#pragma unroll
    for (int j = 0; j < 4; j++) {
        int row = j*64 + vr;
        vS[j] = g_vh + ((size_t)(b*CC + row))*NN + vp;
        vD[j] = sb + (A7_VS + row*72 + vp)*2;
    }

    // ---- ldmatrix addresses (asm operands only)
    unsigned qadr  = sb + ((msub*16 + (lane & 15))*40 + ((lane & 16) >> 1))*2;
    unsigned kbase = sb + (A7_KS + (np*32 + ((lane & 16) >> 1) + (lane & 7))*40
                           + ((lane & 8) ? 8 : 0))*2;
    unsigned ab     = sb + (A7_ES + (mw*32 + (lane & 15))*72 + ((lane & 16) >> 1))*2;
    unsigned bbase  = sb + (A7_VS + (cw*64 + ((lane & 16) >> 1) + (lane & 7))*72
                            + ((lane & 8) ? 8 : 0))*2;
    // ---- Es write pointers (proper C++ shared pointers)
    __half* ew0 = smh + A7_ES + (msub*16 + g)*72;
    __half* ew1 = ew0 + 8*72;

    const float* Mlp = g_Ml2 + b*NN;

    float acc[2][8][4];
#pragma unroll
    for (int ms = 0; ms < 2; ms++)
#pragma unroll
        for (int i = 0; i < 8; i++)
#pragma unroll
            for (int j = 0; j < 4; j++) acc[ms][i][j] = 0.f;

    // prologue: stage 0 (n = 0)
    if (tid < 256) CPA(kD, kS);
#pragma unroll
    for (int j = 0; j < 4; j++) CPA(vD[j], vS[j]);
    CPCOMMIT();
    __syncthreads();    // q tile visible

    // hoist q A-fragments (fixed all kernel)
    unsigned aq[2][4];
    LDSM4(aq[0][0], aq[0][1], aq[0][2], aq[0][3], qadr);
    LDSM4(aq[1][0], aq[1][1], aq[1][2], aq[1][3], qadr + 32);

    for (int it = 0; it < 64; it++) {
        int n0 = it*64;
        if (it + 1 < 64) {
            int n1 = (it + 1)*64;
            unsigned ko = ((it + 1) & 1)*A7_KSB;
            unsigned vo = ((it + 1) & 1)*A7_VSB;
            if (tid < 256) CPA(kD + ko, kS + n1*QKD);
#pragma unroll
            for (int j = 0; j < 4; j++) CPA(vD[j] + vo, vS[j] + n1);
            CPCOMMIT();
            CPWAIT1();
        } else {
            CPWAIT0();
        }
        __syncthreads();
        // ---- logits + exp -> Es
        {
            unsigned kb = kbase + (it & 1)*A7_KSB;
            float d[4][4];
#pragma unroll
            for (int pr = 0; pr < 2; pr++) {
#pragma unroll
                for (int i = 0; i < 4; i++) { d[2*pr][i] = 0.f; d[2*pr+1][i] = 0.f; }
#pragma unroll
                for (int k2 = 0; k2 < 2; k2++) {
                    unsigned b0, b1, c0, c1;
                    LDSM4(b0, b1, c0, c1, kb + pr*1280 + k2*32);
                    mma16(d[2*pr],     aq[k2][0], aq[k2][1], aq[k2][2], aq[k2][3], b0, b1);
                    mma16(d[2*pr + 1], aq[k2][0], aq[k2][1], aq[k2][2], aq[k2][3], c0, c1);
                }
            }
#pragma unroll
            for (int t = 0; t < 4; t++) {
                int nb = np*32 + t*8;
                float2 M2 = *(const float2*)(Mlp + n0 + nb + 2*tig);
                float M0 = M2.x, M1 = M2.y;
                float e0 = fex2(fmaf(d[t][0], L2E, -M0));
                float e1 = fex2(fmaf(d[t][1], L2E, -M1));
                float e2 = fex2(fmaf(d[t][2], L2E, -M0));
                float e3 = fex2(fmaf(d[t][3], L2E, -M1));
                *(__half2*)(ew0 + nb + 2*tig) = __floats2half2_rn(e0, e1);
                *(__half2*)(ew1 + nb + 2*tig) = __floats2half2_rn(e2, e3);
            }
        }
        __syncthreads();
        // ---- PV: acc += Es * Vs
        {
            unsigned vb = bbase + (it & 1)*A7_VSB;
#pragma unroll
            for (int k2 = 0; k2 < 4; k2++) {
                unsigned a0[4], a1[4];
                LDSM4(a0[0], a0[1], a0[2], a0[3], ab + k2*32);
                LDSM4(a1[0], a1[1], a1[2], a1[3], ab + 2304 + k2*32);
#pragma unroll
                for (int pr = 0; pr < 4; pr++) {
                    unsigned b0, b1, c0, c1;
                    LDSM4(b0, b1, c0, c1, vb + pr*2304 + k2*32);
                    mma16(acc[0][2*pr],     a0[0], a0[1], a0[2], a0[3], b0, b1);
                    mma16(acc[1][2*pr],     a1[0], a1[1], a1[2], a1[3], b0, b1);
                    mma16(acc[0][2*pr + 1], a0[0], a0[1], a0[2], a0[3], c0, c1);
                    mma16(acc[1][2*pr + 1], a1[0], a1[1], a1[2], a1[3], c0, c1);
                }
            }
        }
        __syncthreads();
    }
#pragma unroll
    for (int ms = 0; ms < 2; ms++) {
        size_t row = (size_t)(b*NN + m0 + mw*32 + ms*16 + g);
#pragma unroll
        for (int t8 = 0; t8 < 8; t8++) {
            int col = cw*64 + t8*8 + 2*tig;
            *(__half2*)(g_xh + row*CC + col) =
                __floats2half2_rn(acc[ms][t8][0], acc[ms][t8][1]);
            *(__half2*)(g_xh + (row + 8)*CC + col) =
                __floats2half2_rn(acc[ms][t8][2], acc[ms][t8][3]);
        }
    }
}

// ---------------- MLP fp16 (ldmatrix) + LN partials, fp16 output -------------
__global__ void __launch_bounds__(256, 2) mlp5(const float* __restrict__ b1,
                                               const float* __restrict__ b2) {
    extern __shared__ __half smh[];
    __half* Xs  = smh;                   // 64*264
    __half* W1s = Xs  + 64*264;          // 32*264
    __half* Hs  = W1s + 32*264;          // 64*40
    __half* W2s = Hs  + 64*40;           // 256*40

    int m0 = blockIdx.x*64;
    int tid = threadIdx.x, w = tid >> 5, lane = tid & 31, g = lane >> 2, tig = lane & 3;
    int sw = w & 3, np = w >> 2;
    int m2 = w & 1, c4 = w >> 1;

    unsigned aadr1 = s2u(Xs)  + ((sw*16 + (lane & 15))*264 + ((lane & 16) >> 1))*2;
    unsigned badr1 = s2u(W1s) + ((np*16 + ((lane & 16) >> 1) + (lane & 7))*264
                                 + ((lane & 8) ? 8 : 0))*2;
    unsigned hadr  = s2u(Hs)  + ((m2*32 + (lane & 15))*40 + ((lane & 16) >> 1))*2;
    unsigned w2adr = s2u(W2s) + ((c4*64 + ((lane & 16) >> 1) + (lane & 7))*40
                                 + ((lane & 8) ? 8 : 0))*2;

#pragma unroll
    for (int r = 0; r < 8; r++) {
        int e = r*256 + tid; int row = e >> 5, q = e & 31;
        *(uint4*)(Xs + row*264 + q*8) =
            *(const uint4*)(g_xh + (size_t)(m0 + row)*CC + q*8);
    }

    float acc2[2][8][4];
#pragma unroll
    for (int ms = 0; ms < 2; ms++)
#pragma unroll
        for (int i = 0; i < 8; i++)
#pragma unroll
            for (int j = 0; j < 4; j++) acc2[ms][i][j] = 0.f;

    for (int slab = 0; slab < 8; slab++) {
        __syncthreads();
#pragma unroll
        for (int r = 0; r < 16; r++) {
            int e = r*256 + tid; int row = e >> 7, c2 = e & 127;
            *(__half2*)(W1s + row*264 + 2*c2) =
                *(const __half2*)(g_W1h + (slab*32 + row)*CC + 2*c2);
        }
#pragma unroll
        for (int r = 0; r < 16; r++) {
            int e = r*256 + tid; int row = e >> 4, c2 = e & 15;
            *(__half2*)(W2s + row*40 + 2*c2) =
                *(const __half2*)(g_W2h + row*CC + slab*32 + 2*c2);
        }
        __syncthreads();
        float acc1[2][4];
#pragma unroll
        for (int t = 0; t < 2; t++)
#pragma unroll
            for (int j = 0; j < 4; j++) acc1[t][j] = 0.f;
#pragma unroll
        for (int k2 = 0; k2 < 16; k2++) {
            unsigned a0, a1, a2, a3, b0, b1, c0, c1;
            LDSM4(a0, a1, a2, a3, aadr1 + k2*32);
            LDSM4(b0, b1, c0, c1, badr1 + k2*32);
            mma16(acc1[0], a0, a1, a2, a3, b0, b1);
            mma16(acc1[1], a0, a1, a2, a3, c0, c1);
        }
#pragma unroll
        for (int t = 0; t < 2; t++) {
            int nb = np*16 + t*8;
            float bb0 = b1[slab*32 + nb + 2*tig];
            float bb1 = b1[slab*32 + nb + 2*tig + 1];
            *(__half2*)(Hs + (sw*16 + g)*40 + nb + 2*tig) =
                __floats2half2_rn(fmaxf(acc1[t][0] + bb0, 0.f), fmaxf(acc1[t][1] + bb1, 0.f));
            *(__half2*)(Hs + (sw*16 + 8 + g)*40 + nb + 2*tig) =
                __floats2half2_rn(fmaxf(acc1[t][2] + bb0, 0.f), fmaxf(acc1[t][3] + bb1, 0.f));
        }
        __syncthreads();
#pragma unroll
        for (int k2 = 0; k2 < 2; k2++) {
            unsigned a0[4], a1[4];
            LDSM4(a0[0], a0[1], a0[2], a0[3], hadr + k2*32);
            LDSM4(a1[0], a1[1], a1[2], a1[3], hadr + 1280 + k2*32);
#pragma unroll
            for (int pr = 0; pr < 4; pr++) {
                unsigned b0, b1, c0, c1;
                LDSM4(b0, b1, c0, c1, w2adr + pr*1280 + k2*32);
                mma16(acc2[0][2*pr],     a0[0], a0[1], a0[2], a0[3], b0, b1);
                mma16(acc2[1][2*pr],     a1[0], a1[1], a1[2], a1[3], b0, b1);
                mma16(acc2[0][2*pr + 1], a0[0], a0[1], a0[2], a0[3], c0, c1);
                mma16(acc2[1][2*pr + 1], a1[0], a1[1], a1[2], a1[3], c0, c1);
            }
        }
    }
    float bs = 0.f, bqq = 0.f;
#pragma unroll
    for (int ms = 0; ms < 2; ms++) {
        int row = m0 + m2*32 + ms*16 + g;
#pragma unroll
        for (int t8 = 0; t8 < 8; t8++) {
            int col = c4*64 + t8*8 + 2*tig;
            float v0 = acc2[ms][t8][0] + b2[col];
            float v1 = acc2[ms][t8][1] + b2[col + 1];
            float v2 = acc2[ms][t8][2] + b2[col];
            float v3 = acc2[ms][t8][3] + b2[col + 1];
            *(__half2*)(g_mlph + (size_t)row*CC + col)       = __floats2half2_rn(v0, v1);
            *(__half2*)(g_mlph + (size_t)(row + 8)*CC + col) = __floats2half2_rn(v2, v3);
            bs  += v0 + v1 + v2 + v3;
            bqq += v0*v0 + v1*v1 + v2*v2 + v3*v3;
        }
    }
    __syncthreads();
    float* red = (float*)smh;
    red[tid] = bs; red[256 + tid] = bqq;
    __syncthreads();
    for (int st = 128; st > 0; st >>= 1) {
        if (tid < st) { red[tid] += red[tid + st]; red[256 + tid] += red[256 + tid + st]; }
        __syncthreads();
    }
    if (tid == 0) {
        g_red[blockIdx.x*2 + 0] = red[0];
        g_red[blockIdx.x*2 + 1] = red[256];
    }
}

// ---------------- LayerNorm --------------------------------------------------
__global__ void ln_final() {
    __shared__ float ss[64], sq[64];
    int b = blockIdx.x, t = threadIdx.x;
    ss[t] = g_red[(b*64 + t)*2 + 0];
    sq[t] = g_red[(b*64 + t)*2 + 1];
    __syncthreads();
    for (int st = 32; st > 0; st >>= 1) {
        if (t < st) { ss[t] += ss[t + st]; sq[t] += sq[t + st]; }
        __syncthreads();
    }
    if (t == 0) {
        const float inv = 1.0f / (float)(NN * CC);
        float mean = ss[0] * inv;
        float var  = sq[0] * inv - mean*mean;
        g_mv[b*2 + 0] = mean;
        g_mv[b*2 + 1] = rsqrtf(var + 1e-5f);
    }
}

__global__ void ln_apply(const float* __restrict__ gamma,
                         const float* __restrict__ beta,
                         float* __restrict__ out) {
    __shared__ float s[32][33];
    int b = blockIdx.z, c0 = blockIdx.y*32, n0 = blockIdx.x*32;
    int tx = threadIdx.x, ty = threadIdx.y;
    float mean = g_mv[b*2], rstd = g_mv[b*2 + 1];
#pragma unroll
    for (int r = 0; r < 4; r++) {
        int n = n0 + ty + 8*r;
        s[ty + 8*r][tx] = __half2float(g_mlph[(size_t)(b*NN + n)*CC + c0 + tx]);
    }
    __syncthreads();
#pragma unroll
    for (int r = 0; r < 4; r++) {
        int c = c0 + ty + 8*r;
        int n = n0 + tx;
        float v = s[tx][ty + 8*r];
        size_t gi = (size_t)c*NN + n;
        out[(size_t)b*CC*NN + gi] = (v - mean)*rstd*gamma[gi] + beta[gi];
    }
}

// ---------------- launch ----------------------------------------------------
extern "C" void kernel_launch(void* const* d_in, const int* in_sizes, int n_in,
                              void* d_out, int out_size) {
    const float* x     = (const float*)d_in[0];
    const float* Wq    = (const float*)d_in[1];
    const float* bq    = (const float*)d_in[2];
    const float* Wk    = (const float*)d_in[3];
    const float* bk    = (const float*)d_in[4];
    const float* Wv    = (const float*)d_in[5];
    const float* bv    = (const float*)d_in[6];
    const float* W1    = (const float*)d_in[7];
    const float* b1    = (const float*)d_in[8];
    const float* W2    = (const float*)d_in[9];
    const float* b2    = (const float*)d_in[10];
    const float* gamma = (const float*)d_in[11];
    const float* beta  = (const float*)d_in[12];
    float* out = (float*)d_out;

    const int stats_smem = 20992;
    const int attn_smem  = 112640;
    const int mlp_smem   = (64*264 + 32*264 + 64*40 + 256*40)*2;  // 76288
    cudaFuncSetAttribute(stats6,   cudaFuncAttributeMaxDynamicSharedMemorySize, stats_smem);
    cudaFuncSetAttribute(attnout7, cudaFuncAttributeMaxDynamicSharedMemorySize, attn_smem);
    cudaFuncSetAttribute(mlp5,     cudaFuncAttributeMaxDynamicSharedMemorySize, mlp_smem);

    wprep<<<(2*CC*CC)/256, 256>>>(W1, W2);
    qkv_mma<<<dim3(NN/64, 5, BB), 256>>>(x, Wq, bq, Wk, bk, Wv, bv);
    bound_norms<<<(BB*NN)/256, 256>>>();
    stats6<<<dim3(NN/128, BB), 256, stats_smem>>>();
    vprep<<<dim3(NN/32, CC/32, BB), dim3(32, 8)>>>();
    attnout7<<<dim3(NN/128, BB), 512, attn_smem>>>();
    mlp5<<<(BB*NN)/64, 256, mlp_smem>>>(b1, b2);
    ln_final<<<BB, 64>>>();
    ln_apply<<<dim3(NN/32, CC/32, BB), dim3(32, 8)>>>(gamma, beta, out);
}